// round 1
// baseline (speedup 1.0000x reference)
#include <cuda_runtime.h>
#include <cstdint>

#define V_THRESHOLD 1.0f
#define EPS_CLIP 1e-8f

// ---------------------------------------------------------------------------
// Kernel 1: integrate-and-fire scan over T timesteps.
// Each thread owns 4 contiguous (n,d) elements (float4) and scans T in regs.
// Reads/writes are fully coalesced: at each t, consecutive threads touch
// consecutive float4s inside a contiguous 64MB plane.
// ---------------------------------------------------------------------------
template <int T>
__global__ void __launch_bounds__(256) if_scan_kernel(
    const float4* __restrict__ x,   // [T, ND/4]
    float4* __restrict__ s,         // [T, ND/4]
    int nd4)
{
    int i = blockIdx.x * blockDim.x + threadIdx.x;
    if (i >= nd4) return;

    float4 mem = make_float4(0.f, 0.f, 0.f, 0.f);

#pragma unroll
    for (int t = 0; t < T; ++t) {
        size_t off = (size_t)t * nd4 + i;
        float4 xv = x[off];
        mem.x += xv.x; mem.y += xv.y; mem.z += xv.z; mem.w += xv.w;

        float4 sp;
        sp.x = mem.x > V_THRESHOLD ? 1.0f : 0.0f;
        sp.y = mem.y > V_THRESHOLD ? 1.0f : 0.0f;
        sp.z = mem.z > V_THRESHOLD ? 1.0f : 0.0f;
        sp.w = mem.w > V_THRESHOLD ? 1.0f : 0.0f;

        mem.x -= V_THRESHOLD * sp.x;
        mem.y -= V_THRESHOLD * sp.y;
        mem.z -= V_THRESHOLD * sp.z;
        mem.w -= V_THRESHOLD * sp.w;

        s[off] = sp;
    }
}

// Generic (non-unrolled) fallback in case T != 16 at runtime.
__global__ void __launch_bounds__(256) if_scan_kernel_dyn(
    const float4* __restrict__ x,
    float4* __restrict__ s,
    int nd4, int T)
{
    int i = blockIdx.x * blockDim.x + threadIdx.x;
    if (i >= nd4) return;

    float4 mem = make_float4(0.f, 0.f, 0.f, 0.f);
    for (int t = 0; t < T; ++t) {
        size_t off = (size_t)t * nd4 + i;
        float4 xv = x[off];
        mem.x += xv.x; mem.y += xv.y; mem.z += xv.z; mem.w += xv.w;
        float4 sp;
        sp.x = mem.x > V_THRESHOLD ? 1.0f : 0.0f;
        sp.y = mem.y > V_THRESHOLD ? 1.0f : 0.0f;
        sp.z = mem.z > V_THRESHOLD ? 1.0f : 0.0f;
        sp.w = mem.w > V_THRESHOLD ? 1.0f : 0.0f;
        mem.x -= V_THRESHOLD * sp.x;
        mem.y -= V_THRESHOLD * sp.y;
        mem.z -= V_THRESHOLD * sp.z;
        mem.w -= V_THRESHOLD * sp.w;
        s[off] = sp;
    }
}

// ---------------------------------------------------------------------------
// Kernel 2: Lorentz expmap. One warp per row (D = 256 floats = 64 float4;
// 32 lanes x 2 float4 each). Minkowski inner via warp shfl-xor reduction.
//   inner = -v0^2 + sum_{i>=1} v_i^2  = (sum_i v_i^2) - 2*v0^2
//   vnorm = sqrt(max(inner, EPS))
//   out   = cosh(vnorm)*z + sinh(vnorm)/vnorm * v
// ---------------------------------------------------------------------------
__global__ void __launch_bounds__(256) lorentz_expmap_kernel(
    const float4* __restrict__ v,   // [N, 64]
    const float4* __restrict__ z,   // [N, 64]
    float4* __restrict__ out,       // [N, 64]
    int N)
{
    int gwarp = (blockIdx.x * blockDim.x + threadIdx.x) >> 5;
    int lane  = threadIdx.x & 31;
    if (gwarp >= N) return;

    size_t base = (size_t)gwarp * 64;
    float4 va = v[base + lane];
    float4 vb = v[base + lane + 32];

    float sum = va.x * va.x + va.y * va.y + va.z * va.z + va.w * va.w
              + vb.x * vb.x + vb.y * vb.y + vb.z * vb.z + vb.w * vb.w;
    // Minkowski: time-like component (row element 0, held by lane 0 as va.x)
    if (lane == 0) sum -= 2.0f * va.x * va.x;

#pragma unroll
    for (int o = 16; o > 0; o >>= 1)
        sum += __shfl_xor_sync(0xFFFFFFFFu, sum, o);

    float vn = sqrtf(fmaxf(sum, EPS_CLIP));
    float ch = coshf(vn);
    float sh = sinhf(vn) / vn;

    float4 za = z[base + lane];
    float4 zb = z[base + lane + 32];

    float4 oa, ob;
    oa.x = ch * za.x + sh * va.x;
    oa.y = ch * za.y + sh * va.y;
    oa.z = ch * za.z + sh * va.z;
    oa.w = ch * za.w + sh * va.w;
    ob.x = ch * zb.x + sh * vb.x;
    ob.y = ch * zb.y + sh * vb.y;
    ob.z = ch * zb.z + sh * vb.z;
    ob.w = ch * zb.w + sh * vb.w;

    out[base + lane]      = oa;
    out[base + lane + 32] = ob;
}

// ---------------------------------------------------------------------------
// kernel_launch
//   d_in[0] = x_seq [T, N, D] fp32
//   d_in[1] = v_seq [N, D]    fp32
//   d_in[2] = z_seq [N, D]    fp32
//   d_out   = s_seq [T, N, D] fp32  followed by  z_out [N, D] fp32
// ---------------------------------------------------------------------------
extern "C" void kernel_launch(void* const* d_in, const int* in_sizes, int n_in,
                              void* d_out, int out_size)
{
    const float* x = (const float*)d_in[0];
    const float* v = (const float*)d_in[1];
    const float* z = (const float*)d_in[2];
    float* out = (float*)d_out;

    const int ND = in_sizes[1];            // N * D
    const int T  = in_sizes[0] / ND;       // 16
    const int D  = 256;
    const int N  = ND / D;

    float* s_out = out;                    // [T, N, D]
    float* z_out = out + (size_t)T * ND;   // [N, D]

    // IF scan
    int nd4 = ND / 4;
    int threads = 256;
    int blocks = (nd4 + threads - 1) / threads;
    if (T == 16) {
        if_scan_kernel<16><<<blocks, threads>>>(
            (const float4*)x, (float4*)s_out, nd4);
    } else {
        if_scan_kernel_dyn<<<blocks, threads>>>(
            (const float4*)x, (float4*)s_out, nd4, T);
    }

    // Lorentz expmap: 8 warps (rows) per 256-thread block
    int warps_per_block = threads / 32;
    int eblocks = (N + warps_per_block - 1) / warps_per_block;
    lorentz_expmap_kernel<<<eblocks, threads>>>(
        (const float4*)v, (const float4*)z, (float4*)z_out, N);
}

// round 2
// speedup vs baseline: 1.0204x; 1.0204x over previous
#include <cuda_runtime.h>
#include <cstdint>

#define V_THRESHOLD 1.0f
#define EPS_CLIP 1e-8f

// ---------------------------------------------------------------------------
// Fused kernel.
//   Blocks [0, scan_blocks)            : IF scan (thread owns one float4
//                                        column, scans T=16 in registers).
//   Blocks [scan_blocks, scan_blocks+e): Lorentz expmap (one warp per row).
// Both halves are pure streaming -> use evict-first (.cs) loads/stores.
// ---------------------------------------------------------------------------

__device__ __forceinline__ float4 ldcs4(const float4* p) {
    return __ldcs(p);
}
__device__ __forceinline__ void stcs4(float4* p, float4 v) {
    __stcs(p, v);
}

template <int T>
__device__ __forceinline__ void if_scan_body(
    const float4* __restrict__ x, float4* __restrict__ s,
    int i, int nd4)
{
    float4 mem = make_float4(0.f, 0.f, 0.f, 0.f);
#pragma unroll
    for (int t = 0; t < T; ++t) {
        size_t off = (size_t)t * nd4 + i;
        float4 xv = ldcs4(x + off);
        mem.x += xv.x; mem.y += xv.y; mem.z += xv.z; mem.w += xv.w;

        float4 sp;
        sp.x = mem.x > V_THRESHOLD ? 1.0f : 0.0f;
        sp.y = mem.y > V_THRESHOLD ? 1.0f : 0.0f;
        sp.z = mem.z > V_THRESHOLD ? 1.0f : 0.0f;
        sp.w = mem.w > V_THRESHOLD ? 1.0f : 0.0f;

        mem.x -= sp.x;  // V_THRESHOLD == 1.0f
        mem.y -= sp.y;
        mem.z -= sp.z;
        mem.w -= sp.w;

        stcs4(s + off, sp);
    }
}

__device__ __forceinline__ void expmap_body(
    const float4* __restrict__ v, const float4* __restrict__ z,
    float4* __restrict__ out, int row)
{
    int lane = threadIdx.x & 31;
    size_t base = (size_t)row * 64;

    float4 va = ldcs4(v + base + lane);
    float4 vb = ldcs4(v + base + lane + 32);

    float sum = va.x * va.x + va.y * va.y + va.z * va.z + va.w * va.w
              + vb.x * vb.x + vb.y * vb.y + vb.z * vb.z + vb.w * vb.w;
    if (lane == 0) sum -= 2.0f * va.x * va.x;   // Minkowski time component

#pragma unroll
    for (int o = 16; o > 0; o >>= 1)
        sum += __shfl_xor_sync(0xFFFFFFFFu, sum, o);

    float vn = sqrtf(fmaxf(sum, EPS_CLIP));
    float ch = coshf(vn);
    float sh = sinhf(vn) / vn;

    float4 za = ldcs4(z + base + lane);
    float4 zb = ldcs4(z + base + lane + 32);

    float4 oa, ob;
    oa.x = fmaf(ch, za.x, sh * va.x);
    oa.y = fmaf(ch, za.y, sh * va.y);
    oa.z = fmaf(ch, za.z, sh * va.z);
    oa.w = fmaf(ch, za.w, sh * va.w);
    ob.x = fmaf(ch, zb.x, sh * vb.x);
    ob.y = fmaf(ch, zb.y, sh * vb.y);
    ob.z = fmaf(ch, zb.z, sh * vb.z);
    ob.w = fmaf(ch, zb.w, sh * vb.w);

    stcs4(out + base + lane,      oa);
    stcs4(out + base + lane + 32, ob);
}

template <int T>
__global__ void __launch_bounds__(256) fused_kernel(
    const float4* __restrict__ x,   // [T, ND/4]
    const float4* __restrict__ v,   // [N, 64]
    const float4* __restrict__ z,   // [N, 64]
    float4* __restrict__ s,         // [T, ND/4]
    float4* __restrict__ zout,      // [N, 64]
    int nd4, int N, int scan_blocks)
{
    if (blockIdx.x < (unsigned)scan_blocks) {
        int i = blockIdx.x * blockDim.x + threadIdx.x;
        if (i < nd4) if_scan_body<T>(x, s, i, nd4);
    } else {
        int eb = blockIdx.x - scan_blocks;
        int row = eb * (blockDim.x >> 5) + (threadIdx.x >> 5);
        if (row < N) expmap_body(v, z, zout, row);
    }
}

// Dynamic-T fallback (T != 16), two separate plain kernels.
__global__ void __launch_bounds__(256) if_scan_dyn(
    const float4* __restrict__ x, float4* __restrict__ s, int nd4, int T)
{
    int i = blockIdx.x * blockDim.x + threadIdx.x;
    if (i >= nd4) return;
    float4 mem = make_float4(0.f, 0.f, 0.f, 0.f);
    for (int t = 0; t < T; ++t) {
        size_t off = (size_t)t * nd4 + i;
        float4 xv = __ldcs(x + off);
        mem.x += xv.x; mem.y += xv.y; mem.z += xv.z; mem.w += xv.w;
        float4 sp;
        sp.x = mem.x > V_THRESHOLD ? 1.0f : 0.0f;
        sp.y = mem.y > V_THRESHOLD ? 1.0f : 0.0f;
        sp.z = mem.z > V_THRESHOLD ? 1.0f : 0.0f;
        sp.w = mem.w > V_THRESHOLD ? 1.0f : 0.0f;
        mem.x -= V_THRESHOLD * sp.x;
        mem.y -= V_THRESHOLD * sp.y;
        mem.z -= V_THRESHOLD * sp.z;
        mem.w -= V_THRESHOLD * sp.w;
        __stcs(s + off, sp);
    }
}

__global__ void __launch_bounds__(256) expmap_only(
    const float4* __restrict__ v, const float4* __restrict__ z,
    float4* __restrict__ out, int N)
{
    int row = blockIdx.x * (blockDim.x >> 5) + (threadIdx.x >> 5);
    if (row < N) expmap_body(v, z, out, row);
}

// ---------------------------------------------------------------------------
// kernel_launch
//   d_in[0] = x_seq [T, N, D] fp32
//   d_in[1] = v_seq [N, D]    fp32
//   d_in[2] = z_seq [N, D]    fp32
//   d_out   = s_seq [T, N, D] fp32  followed by  z_out [N, D] fp32
// ---------------------------------------------------------------------------
extern "C" void kernel_launch(void* const* d_in, const int* in_sizes, int n_in,
                              void* d_out, int out_size)
{
    const float* x = (const float*)d_in[0];
    const float* v = (const float*)d_in[1];
    const float* z = (const float*)d_in[2];
    float* out = (float*)d_out;

    const int ND = in_sizes[1];            // N * D
    const int T  = in_sizes[0] / ND;       // 16
    const int D  = 256;
    const int N  = ND / D;

    float* s_out = out;                    // [T, N, D]
    float* z_out = out + (size_t)T * ND;   // [N, D]

    const int threads = 256;
    const int nd4 = ND / 4;
    const int scan_blocks = (nd4 + threads - 1) / threads;
    const int wpb = threads / 32;
    const int exp_blocks = (N + wpb - 1) / wpb;

    if (T == 16 && D == 256) {
        fused_kernel<16><<<scan_blocks + exp_blocks, threads>>>(
            (const float4*)x, (const float4*)v, (const float4*)z,
            (float4*)s_out, (float4*)z_out, nd4, N, scan_blocks);
    } else {
        if_scan_dyn<<<scan_blocks, threads>>>(
            (const float4*)x, (float4*)s_out, nd4, T);
        expmap_only<<<exp_blocks, threads>>>(
            (const float4*)v, (const float4*)z, (float4*)z_out, N);
    }
}